// round 5
// baseline (speedup 1.0000x reference)
#include <cuda_runtime.h>

namespace {

constexpr int H  = 64;
constexpr int Fd = 8;
constexpr int Tn = 512;
constexpr int Pn = 64;
constexpr int NT = 256;
constexpr int NBMAX = 4;
constexpr int HP = 68;      // padded h row (16B aligned, conflict-staggered)

using u64 = unsigned long long;

__device__ __forceinline__ u64 ffma2(u64 a, u64 b, u64 c) {
    u64 d;
    asm("fma.rn.f32x2 %0, %1, %2, %3;" : "=l"(d) : "l"(a), "l"(b), "l"(c));
    return d;
}
__device__ __forceinline__ u64 pack2(float lo, float hi) {
    u64 d;
    asm("mov.b64 %0, {%1, %2};" : "=l"(d) : "f"(lo), "f"(hi));
    return d;
}
__device__ __forceinline__ float hsum2(u64 v) {
    float lo, hi;
    asm("mov.b64 {%0, %1}, %2;" : "=f"(lo), "=f"(hi) : "l"(v));
    return lo + hi;
}
__device__ __forceinline__ float tanh_a(float x) {
    float y;
    asm("tanh.approx.f32 %0, %1;" : "=f"(y) : "f"(x));
    return y;
}
__device__ __forceinline__ float sig_a(float x) {
    return fmaf(tanh_a(0.5f * x), 0.5f, 0.5f);
}

__device__ __forceinline__ void load_w(
    const float* __restrict__ Whh, const float* __restrict__ Wih,
    const float* __restrict__ bih, const float* __restrict__ bhh,
    int j, u64 w2[32], u64 wx[4], u64& bias2)
{
    const ulonglong2* wp = (const ulonglong2*)(Whh + j * H);
#pragma unroll
    for (int k = 0; k < 16; k++) {
        ulonglong2 v = __ldg(wp + k);
        w2[2 * k] = v.x; w2[2 * k + 1] = v.y;
    }
    const ulonglong2* wi = (const ulonglong2*)(Wih + j * Fd);
    ulonglong2 v0 = __ldg(wi), v1 = __ldg(wi + 1);
    wx[0] = v0.x; wx[1] = v0.y; wx[2] = v1.x; wx[3] = v1.y;
    bias2 = pack2(bih[j] + bhh[j], 0.0f);
}

template<int NB_>
__device__ __forceinline__ void gate_mm(
    const u64 w2[32], const u64 wx[4], u64 bias2,
    const float (*__restrict__ sh)[HP], const float (*__restrict__ sx)[Fd],
    u64 acc[NB_])
{
#pragma unroll
    for (int b = 0; b < NB_; b++) {
        ulonglong2 xa = *(const ulonglong2*)&sx[b][0];
        ulonglong2 xb = *(const ulonglong2*)&sx[b][4];
        u64 a = ffma2(wx[0], xa.x, bias2);
        a = ffma2(wx[1], xa.y, a);
        a = ffma2(wx[2], xb.x, a);
        a = ffma2(wx[3], xb.y, a);
        acc[b] = a;
    }
    ulonglong2 hv[2][NB_];
#pragma unroll
    for (int b = 0; b < NB_; b++) hv[0][b] = *(const ulonglong2*)&sh[b][0];
#pragma unroll
    for (int kc = 0; kc < 16; kc++) {
        const int cur = kc & 1, nxt = cur ^ 1;
        if (kc < 15) {
#pragma unroll
            for (int b = 0; b < NB_; b++)
                hv[nxt][b] = *(const ulonglong2*)&sh[b][(kc + 1) * 4];
        }
        u64 wlo = w2[2 * kc], whi = w2[2 * kc + 1];
#pragma unroll
        for (int b = 0; b < NB_; b++) {
            acc[b] = ffma2(wlo, hv[cur][b].x, acc[b]);
            acc[b] = ffma2(whi, hv[cur][b].y, acc[b]);
        }
    }
}

template<int NB_>
__device__ __forceinline__ void run_lstm(
    int b0,
    const float* __restrict__ input,
    const float* __restrict__ eWih, const float* __restrict__ eWhh,
    const float* __restrict__ ebih, const float* __restrict__ ebhh,
    const float* __restrict__ dWih, const float* __restrict__ dWhh,
    const float* __restrict__ dbih, const float* __restrict__ dbhh,
    const float* __restrict__ fcW,  const float* __restrict__ fcb,
    float* __restrict__ out,
    float (*__restrict__ sh0)[HP], float (*__restrict__ sh1)[HP],
    float (*__restrict__ sg)[4][65],
    float (*__restrict__ sx)[Fd], float (*__restrict__ sfcW)[H],
    float* __restrict__ sfcb)
{
    const int tid  = threadIdx.x;
    const int lane = tid & 31;
    const int wrp  = tid >> 5;
    const int g    = lane >> 3;            // gate index this thread's row belongs to
    const int uu8  = 8 * wrp + (lane & 7); // hidden unit (0..63)
    const int j    = 64 * g + uu8;         // gate row owned
    const int ab   = lane >> 3;            // activation: batch row owned (== g)
    // activation unit = uu8 (same lanes)

    ((float*)sfcW)[tid]      = fcW[tid];
    ((float*)sfcW)[tid + NT] = fcW[tid + NT];
    if (tid < Fd) sfcb[tid] = fcb[tid];

    if (ab < NB_) sh0[ab][uu8] = 0.0f;
    float c = 0.0f;

    u64 w2[32], wx[4], bias2;
    load_w(eWhh, eWih, ebih, ebhh, j, w2, wx, bias2);

    const bool xth = tid < NB_ * Fd;
    const int  xb  = tid >> 3;
    const int  xf  = tid & 7;
    const float* xptr = input + (size_t)(b0 + (xth ? xb : 0)) * Tn * Fd + xf;
    float xreg = xth ? __ldg(xptr) : 0.0f;

    float (*shA)[HP] = sh0;   // read buffer
    float (*shB)[HP] = sh1;   // write buffer

    // =================== encoder ===================
    for (int t = 0; t < Tn; t++) {
        if (xth) sx[xb][xf] = xreg;
        __syncthreads();                 // x(t) + h(t-1) visible everywhere
        if (xth && t + 1 < Tn) xreg = __ldg(xptr + (size_t)(t + 1) * Fd);

        u64 acc[NB_];
        gate_mm<NB_>(w2, wx, bias2, shA, sx, acc);
#pragma unroll
        for (int b = 0; b < NB_; b++) sg[b][g][uu8] = hsum2(acc[b]);
        __syncwarp();                    // all 4 gates of my unit are warp-local

        if (ab < NB_) {
            float gi = sg[ab][0][uu8];
            float gf = sg[ab][1][uu8];
            float gg = sg[ab][2][uu8];
            float go = sg[ab][3][uu8];
            c = sig_a(gf) * c + sig_a(gi) * tanh_a(gg);
            shB[ab][uu8] = sig_a(go) * tanh_a(c);
        }
        float (*tmp)[HP] = shA; shA = shB; shB = tmp;
    }
    // T even: final h in shA; sx holds x[:, T-1, :]

    load_w(dWhh, dWih, dbih, dbhh, j, w2, wx, bias2);

    // =================== decoder ===================
    for (int p = 0; p < Pn; p++) {
        __syncthreads();                 // h + x visible
        u64 acc[NB_];
        gate_mm<NB_>(w2, wx, bias2, shA, sx, acc);
#pragma unroll
        for (int b = 0; b < NB_; b++) sg[b][g][uu8] = hsum2(acc[b]);
        __syncwarp();

        if (ab < NB_) {
            float gi = sg[ab][0][uu8];
            float gf = sg[ab][1][uu8];
            float gg = sg[ab][2][uu8];
            float go = sg[ab][3][uu8];
            c = sig_a(gf) * c + sig_a(gi) * tanh_a(gg);
            shB[ab][uu8] = sig_a(go) * tanh_a(c);
        }
        __syncthreads();                 // h_new complete

        if (xth) {                       // pred = h_new @ fcW^T + fcb
            float a = sfcb[xf];
            const float4* hr = (const float4*)&shB[xb][0];
            const float4* wr = (const float4*)&sfcW[xf][0];
#pragma unroll
            for (int k = 0; k < 16; k++) {
                float4 hv = hr[k], wv = wr[k];
                a = fmaf(hv.x, wv.x, a);
                a = fmaf(hv.y, wv.y, a);
                a = fmaf(hv.z, wv.z, a);
                a = fmaf(hv.w, wv.w, a);
            }
            out[((size_t)(b0 + xb) * Pn + p) * Fd + xf] = a;
            sx[xb][xf] = a;
        }
        float (*tmp)[HP] = shA; shA = shB; shB = tmp;
        // next iteration's leading barrier orders sx/h
    }
}

__global__ void __launch_bounds__(NT, 2)
seq2seq_lstm_kernel(
    const float* __restrict__ input,
    const float* __restrict__ eWih, const float* __restrict__ eWhh,
    const float* __restrict__ ebih, const float* __restrict__ ebhh,
    const float* __restrict__ dWih, const float* __restrict__ dWhh,
    const float* __restrict__ dbih, const float* __restrict__ dbhh,
    const float* __restrict__ fcW,  const float* __restrict__ fcb,
    float* __restrict__ out)
{
    __shared__ float sh0[NBMAX][HP];
    __shared__ float sh1[NBMAX][HP];
    __shared__ float sg[NBMAX][4][65];
    __shared__ float sx[NBMAX][Fd];
    __shared__ float sfcW[Fd][H];
    __shared__ float sfcb[Fd];

    const int bid = blockIdx.x;
    if (bid < 136) {
        run_lstm<4>(4 * bid, input, eWih, eWhh, ebih, ebhh,
                    dWih, dWhh, dbih, dbhh, fcW, fcb, out,
                    sh0, sh1, sg, sx, sfcW, sfcb);
    } else {
        int b0 = (bid < 148) ? (544 + 3 * (bid - 136))
                             : (580 + 3 * (bid - 148));
        run_lstm<3>(b0, input, eWih, eWhh, ebih, ebhh,
                    dWih, dWhh, dbih, dbhh, fcW, fcb, out,
                    sh0, sh1, sg, sx, sfcW, sfcb);
    }
}

} // anonymous namespace

extern "C" void kernel_launch(void* const* d_in, const int* in_sizes, int n_in,
                              void* d_out, int out_size)
{
    const float* input = (const float*)d_in[0];
    const float* eWih  = (const float*)d_in[1];
    const float* eWhh  = (const float*)d_in[2];
    const float* ebih  = (const float*)d_in[3];
    const float* ebhh  = (const float*)d_in[4];
    const float* dWih  = (const float*)d_in[5];
    const float* dWhh  = (const float*)d_in[6];
    const float* dbih  = (const float*)d_in[7];
    const float* dbhh  = (const float*)d_in[8];
    const float* fcW   = (const float*)d_in[9];
    const float* fcb   = (const float*)d_in[10];
    float* out = (float*)d_out;

    seq2seq_lstm_kernel<<<296, NT>>>(input, eWih, eWhh, ebih, ebhh,
                                     dWih, dWhh, dbih, dbhh, fcW, fcb, out);
}

// round 6
// speedup vs baseline: 1.1397x; 1.1397x over previous
#include <cuda_runtime.h>

namespace {

constexpr int H  = 64;
constexpr int Fd = 8;
constexpr int Tn = 512;
constexpr int Pn = 64;
constexpr int NT = 256;
constexpr int NBMAX = 4;
constexpr int HP  = 72;     // h row stride: 8*ab bank offset -> conflict-free stores
constexpr int SGS = 264;    // sg row stride (floats), 16B-aligned

using u64 = unsigned long long;

__device__ __forceinline__ u64 ffma2(u64 a, u64 b, u64 c) {
    u64 d;
    asm("fma.rn.f32x2 %0, %1, %2, %3;" : "=l"(d) : "l"(a), "l"(b), "l"(c));
    return d;
}
__device__ __forceinline__ u64 pack2(float lo, float hi) {
    u64 d;
    asm("mov.b64 %0, {%1, %2};" : "=l"(d) : "f"(lo), "f"(hi));
    return d;
}
__device__ __forceinline__ float hsum2(u64 v) {
    float lo, hi;
    asm("mov.b64 {%0, %1}, %2;" : "=f"(lo), "=f"(hi) : "l"(v));
    return lo + hi;
}
__device__ __forceinline__ float tanh_a(float x) {
    float y;
    asm("tanh.approx.f32 %0, %1;" : "=f"(y) : "f"(x));
    return y;
}
__device__ __forceinline__ float sig_a(float x) {
    return fmaf(tanh_a(0.5f * x), 0.5f, 0.5f);
}

__device__ __forceinline__ void load_w(
    const float* __restrict__ Whh, const float* __restrict__ Wih,
    const float* __restrict__ bih, const float* __restrict__ bhh,
    int j, u64 w2[32], u64 wx[4], u64& bias2)
{
    const ulonglong2* wp = (const ulonglong2*)(Whh + j * H);
#pragma unroll
    for (int k = 0; k < 16; k++) {
        ulonglong2 v = __ldg(wp + k);
        w2[2 * k] = v.x; w2[2 * k + 1] = v.y;
    }
    const ulonglong2* wi = (const ulonglong2*)(Wih + j * Fd);
    ulonglong2 v0 = __ldg(wi), v1 = __ldg(wi + 1);
    wx[0] = v0.x; wx[1] = v0.y; wx[2] = v1.x; wx[3] = v1.y;
    bias2 = pack2(bih[j] + bhh[j], 0.0f);
}

template<int NB_>
__device__ __forceinline__ void gate_mm(
    const u64 w2[32], const u64 wx[4], u64 bias2,
    const float (*__restrict__ sh)[HP], const float (*__restrict__ sx)[Fd],
    u64 acc[NB_])
{
#pragma unroll
    for (int b = 0; b < NB_; b++) {
        ulonglong2 xa = *(const ulonglong2*)&sx[b][0];
        ulonglong2 xb = *(const ulonglong2*)&sx[b][4];
        u64 a = ffma2(wx[0], xa.x, bias2);
        a = ffma2(wx[1], xa.y, a);
        a = ffma2(wx[2], xb.x, a);
        a = ffma2(wx[3], xb.y, a);
        acc[b] = a;
    }
    ulonglong2 hv[2][NB_];
#pragma unroll
    for (int b = 0; b < NB_; b++) hv[0][b] = *(const ulonglong2*)&sh[b][0];
#pragma unroll
    for (int kc = 0; kc < 16; kc++) {
        const int cur = kc & 1, nxt = cur ^ 1;
        if (kc < 15) {
#pragma unroll
            for (int b = 0; b < NB_; b++)
                hv[nxt][b] = *(const ulonglong2*)&sh[b][(kc + 1) * 4];
        }
        u64 wlo = w2[2 * kc], whi = w2[2 * kc + 1];
#pragma unroll
        for (int b = 0; b < NB_; b++) {
            acc[b] = ffma2(wlo, hv[cur][b].x, acc[b]);
            acc[b] = ffma2(whi, hv[cur][b].y, acc[b]);
        }
    }
}

template<int NB_>
__device__ __forceinline__ void run_lstm(
    int b0,
    const float* __restrict__ input,
    const float* __restrict__ eWih, const float* __restrict__ eWhh,
    const float* __restrict__ ebih, const float* __restrict__ ebhh,
    const float* __restrict__ dWih, const float* __restrict__ dWhh,
    const float* __restrict__ dbih, const float* __restrict__ dbhh,
    const float* __restrict__ fcW,  const float* __restrict__ fcb,
    float* __restrict__ out,
    float (*__restrict__ sh0)[HP], float (*__restrict__ sh1)[HP],
    float* __restrict__ sg,                 // [NBMAX * SGS]
    float (*__restrict__ sx)[NBMAX][Fd],    // [2][NB][Fd]
    float (*__restrict__ sfcW)[H], float* __restrict__ sfcb)
{
    const int tid  = threadIdx.x;
    const int lane = tid & 31;
    const int wrp  = tid >> 5;
    const int g    = lane >> 3;            // gate index / activation batch row
    const int uu8  = 8 * wrp + (lane & 7); // hidden unit (0..63)
    const int j    = 64 * g + uu8;         // gate row owned

    ((float*)sfcW)[tid]      = fcW[tid];
    ((float*)sfcW)[tid + NT] = fcW[tid + NT];
    if (tid < Fd) sfcb[tid] = fcb[tid];

    if (g < NB_) sh0[g][uu8] = 0.0f;
    float c = 0.0f;

    u64 w2[32], wx[4], bias2;
    load_w(eWhh, eWih, ebih, ebhh, j, w2, wx, bias2);

    const bool xth = tid < NB_ * Fd;
    const int  xb  = tid >> 3;
    const int  xf  = tid & 7;
    const float* xptr = input + (size_t)(b0 + (xth ? xb : 0)) * Tn * Fd + xf;
    float xreg = 0.0f;
    if (xth) {
        sx[0][xb][xf] = __ldg(xptr);                 // x(0)
        xreg = __ldg(xptr + Fd);                     // x(1)
    }

    float (*shA)[HP] = sh0;
    float (*shB)[HP] = sh1;
    const int sgi = uu8 * 4 + g;   // my sg slot within a row

    // =================== encoder: 1 CTA barrier / step ===================
    for (int t = 0; t < Tn; t++) {
        __syncthreads();   // h(t-1) in shA and x(t) in sx[t&1] visible
        if (xth && t + 1 < Tn) {
            sx[(t + 1) & 1][xb][xf] = xreg;          // inactive buffer: no race
            if (t + 2 < Tn) xreg = __ldg(xptr + (size_t)(t + 2) * Fd);
        }

        u64 acc[NB_];
        gate_mm<NB_>(w2, wx, bias2, shA, sx[t & 1], acc);
#pragma unroll
        for (int b = 0; b < NB_; b++) sg[b * SGS + sgi] = hsum2(acc[b]);
        __syncwarp();      // all 4 gates of (my batch row g, unit uu8) are warp-local

        if (g < NB_) {
            float4 gt = *(const float4*)&sg[g * SGS + uu8 * 4];  // i,f,g,o
            c = sig_a(gt.y) * c + sig_a(gt.x) * tanh_a(gt.z);
            shB[g][uu8] = sig_a(gt.w) * tanh_a(c);
        }
        float (*tmp)[HP] = shA; shA = shB; shB = tmp;
    }
    // Tn even: final h in shA == sh0; x_last in sx[1]

    load_w(dWhh, dWih, dbih, dbhh, j, w2, wx, bias2);

    // =================== decoder ===================
    for (int p = 0; p < Pn; p++) {
        __syncthreads();   // h in shA, x in sx[1]

        u64 acc[NB_];
        gate_mm<NB_>(w2, wx, bias2, shA, sx[1], acc);
#pragma unroll
        for (int b = 0; b < NB_; b++) sg[b * SGS + sgi] = hsum2(acc[b]);
        __syncwarp();

        if (g < NB_) {
            float4 gt = *(const float4*)&sg[g * SGS + uu8 * 4];
            c = sig_a(gt.y) * c + sig_a(gt.x) * tanh_a(gt.z);
            shB[g][uu8] = sig_a(gt.w) * tanh_a(c);
        }
        __syncthreads();   // h_new complete in shB

        if (xth) {         // pred = h_new @ fcW^T + fcb
            float a = sfcb[xf];
            const float4* hr = (const float4*)&shB[xb][0];
            const float4* wr = (const float4*)&sfcW[xf][0];
#pragma unroll
            for (int k = 0; k < 16; k++) {
                float4 hv = hr[k], wv = wr[k];
                a = fmaf(hv.x, wv.x, a);
                a = fmaf(hv.y, wv.y, a);
                a = fmaf(hv.z, wv.z, a);
                a = fmaf(hv.w, wv.w, a);
            }
            out[((size_t)(b0 + xb) * Pn + p) * Fd + xf] = a;
            sx[1][xb][xf] = a;   // next decoder input
        }
        float (*tmp)[HP] = shA; shA = shB; shB = tmp;
    }
}

__global__ void __launch_bounds__(NT, 2)
seq2seq_lstm_kernel(
    const float* __restrict__ input,
    const float* __restrict__ eWih, const float* __restrict__ eWhh,
    const float* __restrict__ ebih, const float* __restrict__ ebhh,
    const float* __restrict__ dWih, const float* __restrict__ dWhh,
    const float* __restrict__ dbih, const float* __restrict__ dbhh,
    const float* __restrict__ fcW,  const float* __restrict__ fcb,
    float* __restrict__ out)
{
    __shared__ float sh0[NBMAX][HP];
    __shared__ float sh1[NBMAX][HP];
    __shared__ float sg[NBMAX * SGS];
    __shared__ float sx[2][NBMAX][Fd];
    __shared__ float sfcW[Fd][H];
    __shared__ float sfcb[Fd];

    const int bid = blockIdx.x;
    if (bid < 136) {
        run_lstm<4>(4 * bid, input, eWih, eWhh, ebih, ebhh,
                    dWih, dWhh, dbih, dbhh, fcW, fcb, out,
                    sh0, sh1, sg, sx, sfcW, sfcb);
    } else {
        int b0 = (bid < 148) ? (544 + 3 * (bid - 136))
                             : (580 + 3 * (bid - 148));
        run_lstm<3>(b0, input, eWih, eWhh, ebih, ebhh,
                    dWih, dWhh, dbih, dbhh, fcW, fcb, out,
                    sh0, sh1, sg, sx, sfcW, sfcb);
    }
}

} // anonymous namespace

extern "C" void kernel_launch(void* const* d_in, const int* in_sizes, int n_in,
                              void* d_out, int out_size)
{
    const float* input = (const float*)d_in[0];
    const float* eWih  = (const float*)d_in[1];
    const float* eWhh  = (const float*)d_in[2];
    const float* ebih  = (const float*)d_in[3];
    const float* ebhh  = (const float*)d_in[4];
    const float* dWih  = (const float*)d_in[5];
    const float* dWhh  = (const float*)d_in[6];
    const float* dbih  = (const float*)d_in[7];
    const float* dbhh  = (const float*)d_in[8];
    const float* fcW   = (const float*)d_in[9];
    const float* fcb   = (const float*)d_in[10];
    float* out = (float*)d_out;

    seq2seq_lstm_kernel<<<296, NT>>>(input, eWih, eWhh, ebih, ebhh,
                                     dWih, dWhh, dbih, dbhh, fcW, fcb, out);
}

// round 7
// speedup vs baseline: 1.4366x; 1.2605x over previous
#include <cuda_runtime.h>

namespace {

constexpr int H  = 64;
constexpr int Fd = 8;
constexpr int Tn = 512;
constexpr int Pn = 64;
constexpr int NT = 256;
constexpr int NBMAX = 4;
constexpr int HP  = 72;          // h row stride: conflict-free stores/loads
constexpr int SGS = 260;         // sg b-row stride (floats, 16B aligned)
constexpr int QS  = NBMAX * SGS; // sg quarter-buffer stride

using u64 = unsigned long long;

__device__ __forceinline__ u64 ffma2(u64 a, u64 b, u64 c) {
    u64 d;
    asm("fma.rn.f32x2 %0, %1, %2, %3;" : "=l"(d) : "l"(a), "l"(b), "l"(c));
    return d;
}
__device__ __forceinline__ float hsum2(u64 v) {
    float lo, hi;
    asm("mov.b64 {%0, %1}, %2;" : "=f"(lo), "=f"(hi) : "l"(v));
    return lo + hi;
}
__device__ __forceinline__ float tanh_a(float x) {
    float y;
    asm("tanh.approx.f32 %0, %1;" : "=f"(y) : "f"(x));
    return y;
}
__device__ __forceinline__ float sig_a(float x) {
    return fmaf(tanh_a(0.5f * x), 0.5f, 0.5f);
}

// Per-thread weights: all 4 gate rows of unit u, k-quarter q (chunk-rotated).
struct WReg {
    u64  wh[4][8];   // [gate][2*chunk + half] ; chunk c covers h[16q+4*((c+q)&3)..+4)
    u64  wx[4];      // [gate] ; x feats [2q, 2q+1]
    float bi[4];     // biases of the 4 gate rows (added at activation)
};

__device__ __forceinline__ void load_w(
    const float* __restrict__ Whh, const float* __restrict__ Wih,
    const float* __restrict__ bih, const float* __restrict__ bhh,
    int u, int q, WReg& W)
{
#pragma unroll
    for (int g = 0; g < 4; g++) {
        const int row = 64 * g + u;
        const float* base = Whh + row * H + 16 * q;
#pragma unroll
        for (int c = 0; c < 4; c++) {
            const int cc = (c + q) & 3;
            ulonglong2 v = __ldg((const ulonglong2*)(base + 4 * cc));
            W.wh[g][2 * c]     = v.x;
            W.wh[g][2 * c + 1] = v.y;
        }
        W.wx[g] = __ldg((const u64*)(Wih + row * Fd) + q);
        W.bi[g] = bih[row] + bhh[row];
    }
}

// Gate partials for all NB_ batch rows; writes float4 partial per (q,b,u) to sg.
template<int NB_>
__device__ __forceinline__ void gate_mm(
    const WReg& W,
    const float (*__restrict__ sh)[HP], const float (*__restrict__ sx)[Fd],
    float* __restrict__ sg, int u, int q)
{
#pragma unroll
    for (int b = 0; b < NB_; b++) {
        u64 a0 = 0, a1 = 0, a2 = 0, a3 = 0;
        const u64 xv = *(const u64*)&sx[b][2 * q];
        a0 = ffma2(W.wx[0], xv, a0);
        a1 = ffma2(W.wx[1], xv, a1);
        a2 = ffma2(W.wx[2], xv, a2);
        a3 = ffma2(W.wx[3], xv, a3);
        const float* hb = &sh[b][16 * q];
#pragma unroll
        for (int c = 0; c < 4; c++) {
            const int cc = (c + q) & 3;
            ulonglong2 hv = *(const ulonglong2*)(hb + 4 * cc);
            a0 = ffma2(W.wh[0][2 * c], hv.x, a0);
            a1 = ffma2(W.wh[1][2 * c], hv.x, a1);
            a2 = ffma2(W.wh[2][2 * c], hv.x, a2);
            a3 = ffma2(W.wh[3][2 * c], hv.x, a3);
            a0 = ffma2(W.wh[0][2 * c + 1], hv.y, a0);
            a1 = ffma2(W.wh[1][2 * c + 1], hv.y, a1);
            a2 = ffma2(W.wh[2][2 * c + 1], hv.y, a2);
            a3 = ffma2(W.wh[3][2 * c + 1], hv.y, a3);
        }
        float4 part = make_float4(hsum2(a0), hsum2(a1), hsum2(a2), hsum2(a3));
        *(float4*)&sg[q * QS + b * SGS + u * 4] = part;
    }
}

// Activation for (unit u, batch row q): sum the 4 quarter partials + bias.
__device__ __forceinline__ void activation(
    const float* __restrict__ sg, const WReg& W,
    float (*__restrict__ shB)[HP], int u, int q, float& c)
{
    const int base = q * SGS + u * 4;
    float4 s0 = *(const float4*)&sg[0 * QS + base];
    float4 s1 = *(const float4*)&sg[1 * QS + base];
    float4 s2 = *(const float4*)&sg[2 * QS + base];
    float4 s3 = *(const float4*)&sg[3 * QS + base];
    float gi = s0.x + s1.x + s2.x + s3.x + W.bi[0];
    float gf = s0.y + s1.y + s2.y + s3.y + W.bi[1];
    float gg = s0.z + s1.z + s2.z + s3.z + W.bi[2];
    float go = s0.w + s1.w + s2.w + s3.w + W.bi[3];
    c = sig_a(gf) * c + sig_a(gi) * tanh_a(gg);
    shB[q][u] = sig_a(go) * tanh_a(c);
}

template<int NB_>
__device__ __forceinline__ void run_lstm(
    int b0,
    const float* __restrict__ input,
    const float* __restrict__ eWih, const float* __restrict__ eWhh,
    const float* __restrict__ ebih, const float* __restrict__ ebhh,
    const float* __restrict__ dWih, const float* __restrict__ dWhh,
    const float* __restrict__ dbih, const float* __restrict__ dbhh,
    const float* __restrict__ fcW,  const float* __restrict__ fcb,
    float* __restrict__ out,
    float (*__restrict__ sh0)[HP], float (*__restrict__ sh1)[HP],
    float* __restrict__ sg,
    float (*__restrict__ sx)[NBMAX][Fd],
    float (*__restrict__ sfcW)[H], float* __restrict__ sfcb)
{
    const int tid  = threadIdx.x;
    const int lane = tid & 31;
    const int wrp  = tid >> 5;
    const int l7   = lane & 7;
    const int q    = lane >> 3;          // k-quarter / activation batch row
    const int u    = 8 * wrp + l7;       // hidden unit (0..63)

    ((float*)sfcW)[tid]      = fcW[tid];
    ((float*)sfcW)[tid + NT] = fcW[tid + NT];
    if (tid < Fd) sfcb[tid] = fcb[tid];

    if (q < NB_) sh0[q][u] = 0.0f;
    float c = 0.0f;

    WReg W;
    load_w(eWhh, eWih, ebih, ebhh, u, q, W);

    const bool xth = tid < NB_ * Fd;
    const int  xb  = tid >> 3;
    const int  xf  = tid & 7;
    const float* xptr = input + (size_t)(b0 + (xth ? xb : 0)) * Tn * Fd + xf;
    float xreg = 0.0f;
    if (xth) {
        sx[0][xb][xf] = __ldg(xptr);
        xreg = __ldg(xptr + Fd);
    }

    float (*shA)[HP] = sh0;
    float (*shB)[HP] = sh1;

    // =================== encoder: 1 CTA barrier / step ===================
    for (int t = 0; t < Tn; t++) {
        __syncthreads();   // h(t-1) in shA, x(t) in sx[t&1] visible
        if (xth && t + 1 < Tn) {
            sx[(t + 1) & 1][xb][xf] = xreg;
            if (t + 2 < Tn) xreg = __ldg(xptr + (size_t)(t + 2) * Fd);
        }

        gate_mm<NB_>(W, shA, sx[t & 1], sg, u, q);
        __syncwarp();      // all 4 quarters of unit u are warp-local

        if (q < NB_) activation(sg, W, shB, u, q, c);

        float (*tmp)[HP] = shA; shA = shB; shB = tmp;
    }
    // Tn even: final h in shA; x_last in sx[1]

    load_w(dWhh, dWih, dbih, dbhh, u, q, W);

    // =================== decoder ===================
    for (int p = 0; p < Pn; p++) {
        __syncthreads();   // h in shA, x in sx[1]

        gate_mm<NB_>(W, shA, sx[1], sg, u, q);
        __syncwarp();

        if (q < NB_) activation(sg, W, shB, u, q, c);
        __syncthreads();   // h_new complete in shB

        if (xth) {         // pred = h_new @ fcW^T + fcb
            float a = sfcb[xf];
            const float4* hr = (const float4*)&shB[xb][0];
            const float4* wr = (const float4*)&sfcW[xf][0];
#pragma unroll
            for (int k = 0; k < 16; k++) {
                float4 hv = hr[k], wv = wr[k];
                a = fmaf(hv.x, wv.x, a);
                a = fmaf(hv.y, wv.y, a);
                a = fmaf(hv.z, wv.z, a);
                a = fmaf(hv.w, wv.w, a);
            }
            out[((size_t)(b0 + xb) * Pn + p) * Fd + xf] = a;
            sx[1][xb][xf] = a;
        }
        float (*tmp)[HP] = shA; shA = shB; shB = tmp;
    }
}

__global__ void __launch_bounds__(NT, 2)
seq2seq_lstm_kernel(
    const float* __restrict__ input,
    const float* __restrict__ eWih, const float* __restrict__ eWhh,
    const float* __restrict__ ebih, const float* __restrict__ ebhh,
    const float* __restrict__ dWih, const float* __restrict__ dWhh,
    const float* __restrict__ dbih, const float* __restrict__ dbhh,
    const float* __restrict__ fcW,  const float* __restrict__ fcb,
    float* __restrict__ out)
{
    __shared__ float sh0[NBMAX][HP];
    __shared__ float sh1[NBMAX][HP];
    __shared__ float sg[4 * QS];
    __shared__ float sx[2][NBMAX][Fd];
    __shared__ float sfcW[Fd][H];
    __shared__ float sfcb[Fd];

    const int bid = blockIdx.x;
    if (bid < 136) {
        run_lstm<4>(4 * bid, input, eWih, eWhh, ebih, ebhh,
                    dWih, dWhh, dbih, dbhh, fcW, fcb, out,
                    sh0, sh1, sg, sx, sfcW, sfcb);
    } else {
        int b0 = (bid < 148) ? (544 + 3 * (bid - 136))
                             : (580 + 3 * (bid - 148));
        run_lstm<3>(b0, input, eWih, eWhh, ebih, ebhh,
                    dWih, dWhh, dbih, dbhh, fcW, fcb, out,
                    sh0, sh1, sg, sx, sfcW, sfcb);
    }
}

} // anonymous namespace

extern "C" void kernel_launch(void* const* d_in, const int* in_sizes, int n_in,
                              void* d_out, int out_size)
{
    const float* input = (const float*)d_in[0];
    const float* eWih  = (const float*)d_in[1];
    const float* eWhh  = (const float*)d_in[2];
    const float* ebih  = (const float*)d_in[3];
    const float* ebhh  = (const float*)d_in[4];
    const float* dWih  = (const float*)d_in[5];
    const float* dWhh  = (const float*)d_in[6];
    const float* dbih  = (const float*)d_in[7];
    const float* dbhh  = (const float*)d_in[8];
    const float* fcW   = (const float*)d_in[9];
    const float* fcb   = (const float*)d_in[10];
    float* out = (float*)d_out;

    seq2seq_lstm_kernel<<<296, NT>>>(input, eWih, eWhh, ebih, ebhh,
                                     dWih, dWhh, dbih, dbhh, fcW, fcb, out);
}